// round 11
// baseline (speedup 1.0000x reference)
#include <cuda_runtime.h>
#include <cuda_bf16.h>
#include <math.h>
#include <cstdint>

#define B 8192

typedef unsigned long long ull;

// ---------------- packed f32x2 helpers ----------------
__device__ __forceinline__ ull pack2(float v) {
    ull r; asm("mov.b64 %0, {%1, %1};" : "=l"(r) : "f"(v)); return r;
}
__device__ __forceinline__ void fma2(ull& d, ull a, ull b) {
    asm("fma.rn.f32x2 %0, %1, %2, %0;" : "+l"(d) : "l"(a), "l"(b));
}
__device__ __forceinline__ float2 unpack2(ull v) {
    float2 f; asm("mov.b64 {%0, %1}, %2;" : "=f"(f.x), "=f"(f.y) : "l"(v)); return f;
}

// ---------------- bf16 pack helpers ----------------
__device__ __forceinline__ uint32_t bfpack(float lo, float hi) {
    uint32_t r;
    asm("cvt.rn.bf16x2.f32 %0, %1, %2;" : "=r"(r) : "f"(hi), "f"(lo));
    return r;
}
__device__ __forceinline__ uint32_t bflo(float2 v, uint32_t hipk) {
    const float w0 = __uint_as_float(hipk << 16);
    const float w1 = __uint_as_float(hipk & 0xFFFF0000u);
    return bfpack(v.x - w0, v.y - w1);
}

// ---------------- mma.sync m16n8k16 bf16 ----------------
__device__ __forceinline__ void mma_bf16(float* c, const uint32_t* a, const uint32_t* b) {
    asm volatile(
        "mma.sync.aligned.m16n8k16.row.col.f32.bf16.bf16.f32 "
        "{%0,%1,%2,%3}, {%4,%5,%6,%7}, {%8,%9}, {%0,%1,%2,%3};"
        : "+f"(c[0]), "+f"(c[1]), "+f"(c[2]), "+f"(c[3])
        : "r"(a[0]), "r"(a[1]), "r"(a[2]), "r"(a[3]), "r"(b[0]), "r"(b[1]));
}

// ---------------- global scratch ----------------
__device__ float g_feat[B * 1600];
__device__ float g_wpack[1600 * 64];          // 64-padded: j<5 gate, 5..54 experts, rest 0
#define WTS 296
__device__ __align__(16) __nv_bfloat16 g_wth[64 * WTS];
__device__ __align__(16) __nv_bfloat16 g_wtl[64 * WTS];

// ==================== prep kernels ====================
__global__ void pack_weights_kernel(const float* __restrict__ gw,
                                    const float* __restrict__ ew) {
    int i = blockIdx.x * blockDim.x + threadIdx.x;
    if (i >= 1600 * 64) return;
    int d = i >> 6, j = i & 63;
    float v = 0.0f;
    if (j < 5)       v = gw[d * 5 + j];
    else if (j < 55) {
        int e = (j - 5) / 10, c = (j - 5) % 10;
        v = ew[(e * 1600 + d) * 10 + c];
    }
    g_wpack[i] = v;
}

__global__ void prep_w2t_kernel(const float* __restrict__ w2) {
    int i = blockIdx.x * blockDim.x + threadIdx.x;
    if (i >= 64 * WTS) return;
    int co = i / WTS, k = i - co * WTS;
    float v = (k < 288) ? w2[k * 64 + co] : 0.0f;
    __nv_bfloat16 h = __float2bfloat16_rn(v);
    __nv_bfloat16 l = __float2bfloat16_rn(v - __bfloat162float(h));
    g_wth[i] = h;
    g_wtl[i] = l;
}

// ==================== K1: conv1(FFMA2) + conv2(mma.sync, warp=ntile) ====================
#define SM_H   0                       // 169*34 f32 = 22984 -> pad 22992
#define SM_WH  22992                   // 64*296 bf16 = 37888
#define SM_WL  60880
#define SM_X   98768                   // 784 f32
#define SM_W1  101904
#define SM_B1  103056
#define SM_B2  103184
#define SM_TOTAL 103440
#define SM_D   SM_WH                   // D [112][66] f32 aliases WH after mainloop
#define HSS 34

__global__ __launch_bounds__(256, 2) void conv_mma_kernel(
    const float* __restrict__ x,
    const float* __restrict__ w1,
    const float* __restrict__ b1,
    const float* __restrict__ b2)
{
    extern __shared__ char smc[];
    float* s_h  = (float*)(smc + SM_H);
    float* s_x  = (float*)(smc + SM_X);
    float* s_w1 = (float*)(smc + SM_W1);
    float* s_b1 = (float*)(smc + SM_B1);
    float* s_b2 = (float*)(smc + SM_B2);
    const __nv_bfloat16* s_wh = (const __nv_bfloat16*)(smc + SM_WH);
    const __nv_bfloat16* s_wl = (const __nv_bfloat16*)(smc + SM_WL);
    float* s_D = (float*)(smc + SM_D);

    const int t    = threadIdx.x;
    const int wid  = t >> 5;
    const int lane = t & 31;
    const int bb   = blockIdx.x;

    // ---- stage x, w1, biases, w2t hi/lo ----
    {
        const float* xi = x + bb * 784;
        for (int i = t; i < 784; i += 256) s_x[i] = xi[i];
        for (int i = t; i < 288; i += 256) s_w1[i] = w1[i];
        if (t < 32) s_b1[t] = b1[t];
        else if (t < 96) s_b2[t - 32] = b2[t - 32];
        const float4* sh = (const float4*)g_wth;
        const float4* sl = (const float4*)g_wtl;
        float4* dh = (float4*)(smc + SM_WH);
        float4* dl = (float4*)(smc + SM_WL);
        for (int i = t; i < 2368; i += 256) { dh[i] = sh[i]; dl[i] = sl[i]; }
    }
    __syncthreads();

    // ---- conv1 + relu + pool -> s_h (FFMA2) ----
    for (int i = t; i < 676; i += 256) {
        const int cell = i >> 2;
        const int c0   = (i & 3) * 8;
        const int qy = cell / 13, qx = cell - qy * 13;
        const float* xb = s_x + (2 * qy) * 28 + 2 * qx;

        ull a1[4][4];
        #pragma unroll
        for (int p = 0; p < 4; p++)
            #pragma unroll
            for (int j = 0; j < 4; j++) a1[p][j] = 0ULL;

        #pragma unroll
        for (int ky = 0; ky < 3; ky++)
            #pragma unroll
            for (int kx = 0; kx < 3; kx++) {
                const float* xp = xb + ky * 28 + kx;
                const ull xpk[4] = { pack2(xp[0]), pack2(xp[1]), pack2(xp[28]), pack2(xp[29]) };
                const ulonglong2* wq = (const ulonglong2*)(s_w1 + (ky * 3 + kx) * 32 + c0);
                const ulonglong2 wA = wq[0], wB = wq[1];
                const ull wv[4] = { wA.x, wA.y, wB.x, wB.y };
                #pragma unroll
                for (int p = 0; p < 4; p++)
                    #pragma unroll
                    for (int j = 0; j < 4; j++) fma2(a1[p][j], xpk[p], wv[j]);
            }
        float* hb = s_h + cell * HSS + c0;
        #pragma unroll
        for (int j = 0; j < 4; j++) {
            const float2 u0 = unpack2(a1[0][j]), u1 = unpack2(a1[1][j]);
            const float2 u2 = unpack2(a1[2][j]), u3 = unpack2(a1[3][j]);
            float2 v;
            v.x = fmaxf(fmaxf(fmaxf(u0.x, u1.x), fmaxf(u2.x, u3.x)) + s_b1[c0 + 2*j],     0.0f);
            v.y = fmaxf(fmaxf(fmaxf(u0.y, u1.y), fmaxf(u2.y, u3.y)) + s_b1[c0 + 2*j + 1], 0.0f);
            *(float2*)(hb + 2*j) = v;
        }
    }
    __syncthreads();

    // ---- conv2 GEMM: M=112 x N=64 x K=288; warp w = ntile w over all 7 mtiles ----
    const int g  = lane >> 2;          // 0..7
    const int tq = lane & 3;           // 0..3
    const int co = wid * 8 + g;        // this warp's B column for its ntile

    float acc[7][4];
    #pragma unroll
    for (int mt = 0; mt < 7; mt++)
        #pragma unroll
        for (int q = 0; q < 4; q++) acc[mt][q] = 0.0f;

    // row -> h1 cell mapping (row r < 100 -> cell (r/10)*13 + r%10)
    int crow[7][2];
    #pragma unroll
    for (int mt = 0; mt < 7; mt++) {
        const int r0 = mt * 16 + g, r1 = r0 + 8;
        crow[mt][0] = (r0 < 100) ? (r0 / 10) * 13 + (r0 % 10) : 0;
        crow[mt][1] = (r1 < 100) ? (r1 / 10) * 13 + (r1 % 10) : 0;
    }

    #pragma unroll 1
    for (int ks = 0; ks < 18; ks++) {
        const int tap = ks >> 1;
        const int ty = tap / 3, tx = tap - ty * 3;
        const int toff = ty * 13 + tx;
        const int ci0 = (ks & 1) << 4;
        const int kb = ks * 16;

        // B fragments: single ntile per warp
        uint32_t bh[2], bl[2];
        {
            const uint32_t* ph = (const uint32_t*)(s_wh + co * WTS + kb);
            const uint32_t* pl = (const uint32_t*)(s_wl + co * WTS + kb);
            bh[0] = ph[tq];  bh[1] = ph[tq + 4];
            bl[0] = pl[tq];  bl[1] = pl[tq + 4];
        }

        const int col = ci0 + 2 * tq;
        #pragma unroll
        for (int mt = 0; mt < 7; mt++) {
            const float* hp0 = s_h + (crow[mt][0] + toff) * HSS + col;
            const float* hp1 = s_h + (crow[mt][1] + toff) * HSS + col;
            const float2 v00 = *(const float2*)(hp0);
            const float2 v10 = *(const float2*)(hp1);
            const float2 v01 = *(const float2*)(hp0 + 8);
            const float2 v11 = *(const float2*)(hp1 + 8);
            uint32_t ah[4], al[4];
            ah[0] = bfpack(v00.x, v00.y);  al[0] = bflo(v00, ah[0]);
            ah[1] = bfpack(v10.x, v10.y);  al[1] = bflo(v10, ah[1]);
            ah[2] = bfpack(v01.x, v01.y);  al[2] = bflo(v01, ah[2]);
            ah[3] = bfpack(v11.x, v11.y);  al[3] = bflo(v11, ah[3]);

            mma_bf16(acc[mt], ah, bh);
            mma_bf16(acc[mt], al, bh);
            mma_bf16(acc[mt], ah, bl);
        }
    }

    // ---- write D to smem (aliases WH -> barrier first) ----
    __syncthreads();
    {
        const int col = wid * 8 + 2 * tq;
        #pragma unroll
        for (int mt = 0; mt < 7; mt++) {
            const int dr0 = mt * 16 + g;
            *(float2*)(s_D + dr0 * 66 + col)       = make_float2(acc[mt][0], acc[mt][1]);
            *(float2*)(s_D + (dr0 + 8) * 66 + col) = make_float2(acc[mt][2], acc[mt][3]);
        }
    }
    __syncthreads();

    // ---- maxpool + bias + relu -> g_feat (rows r = y*10+x) ----
    if (t < 200) {
        const int cg = t / 25;
        const int pc = t - cg * 25;
        const int co0 = cg * 8;
        const int qy = pc / 5, qx = pc - qy * 5;
        const float* r0p = s_D + ((2 * qy) * 10 + 2 * qx) * 66 + co0;
        const float* r1p = r0p + 66;
        const float* r2p = s_D + ((2 * qy + 1) * 10 + 2 * qx) * 66 + co0;
        const float* r3p = r2p + 66;
        float* fo = g_feat + (bb * 25 + pc) * 64 + co0;
        #pragma unroll
        for (int j = 0; j < 8; j++) {
            const float m = fmaxf(fmaxf(r0p[j], r1p[j]), fmaxf(r2p[j], r3p[j]));
            fo[j] = fmaxf(m + s_b2[co0 + j], 0.0f);
        }
    }
}

// ==================== K2: head GEMM + MoE epilogue — 512 blocks x 16 rows ====================
#define KC 64
#define FS 68
#define STG (16 * FS + KC * 64)        // 1088 + 4096 = 5184 floats per stage
__global__ __launch_bounds__(256) void moe_head_kernel(
    const float* __restrict__ gb,
    const float* __restrict__ eb,
    float* __restrict__ out)
{
    __shared__ float s_stage[2 * STG];     // 10368 floats
    __shared__ float s_l[16 * 65];         // logits, stride 65
    __shared__ float s_bias[64];
    float* s_p = s_stage;                  // 3*64*16 = 3072 partials, alias stage0 after loop

    const int t    = threadIdx.x;
    const int s    = t >> 6;               // k-split 0..3
    const int u    = t & 63;
    const int rg   = u >> 3;
    const int cb   = (u & 7) * 8;          // 8-wide, LDS.128-aligned
    const int r0   = rg * 2;
    const int row0 = blockIdx.x * 16;
    const int kk0  = s * 16;

    if (t < 64) s_bias[t] = (t < 5) ? gb[t] : ((t < 55) ? eb[t - 5] : 0.0f);

    float acc[2][8];
    #pragma unroll
    for (int i = 0; i < 2; i++)
        #pragma unroll
        for (int j = 0; j < 8; j++) acc[i][j] = 0.0f;

    auto load_stage = [&](int chunk, float* buf) {
        const int k0 = chunk * KC;
        float* sf = buf;
        float* sw = buf + 16 * FS;
        {
            const int r = t >> 4, c0 = (t & 15) * 4;
            const float4 v = *(const float4*)(g_feat + (row0 + r) * 1600 + k0 + c0);
            *(float4*)(sf + r * FS + c0) = v;
        }
        {
            const float4* src = (const float4*)(g_wpack + k0 * 64);
            float4* dst = (float4*)sw;
            for (int i = t; i < 1024; i += 256) dst[i] = src[i];
        }
    };

    load_stage(0, s_stage);
    __syncthreads();

    for (int chunk = 0; chunk < 25; chunk++) {
        float* cur = s_stage + (chunk & 1) * STG;
        if (chunk < 24) load_stage(chunk + 1, s_stage + ((chunk + 1) & 1) * STG);

        const float* sf = cur;
        const float* sw = cur + 16 * FS;
        #pragma unroll 4
        for (int kk = kk0; kk < kk0 + 16; kk++) {
            const float f0 = sf[(r0    ) * FS + kk];
            const float f1 = sf[(r0 + 1) * FS + kk];
            const float* wr = sw + kk * 64 + cb;
            const float4 wa = *(const float4*)(wr);
            const float4 wb = *(const float4*)(wr + 4);
            const float wv[8] = { wa.x, wa.y, wa.z, wa.w, wb.x, wb.y, wb.z, wb.w };
            #pragma unroll
            for (int j = 0; j < 8; j++) {
                acc[0][j] = fmaf(f0, wv[j], acc[0][j]);
                acc[1][j] = fmaf(f1, wv[j], acc[1][j]);
            }
        }
        __syncthreads();
    }

    // ---- k-split reduction (s_p aliases stage0; barrier above covers) ----
    if (s > 0) {
        float* pp = s_p + ((s - 1) * 64 + u) * 16;
        #pragma unroll
        for (int i = 0; i < 2; i++)
            #pragma unroll
            for (int j = 0; j < 8; j++) pp[i * 8 + j] = acc[i][j];
    }
    __syncthreads();
    if (s == 0) {
        #pragma unroll
        for (int q = 0; q < 3; q++) {
            const float* pp = s_p + (q * 64 + u) * 16;
            #pragma unroll
            for (int i = 0; i < 2; i++)
                #pragma unroll
                for (int j = 0; j < 8; j++) acc[i][j] += pp[i * 8 + j];
        }
        #pragma unroll
        for (int i = 0; i < 2; i++)
            #pragma unroll
            for (int j = 0; j < 8; j++)
                s_l[(r0 + i) * 65 + cb + j] = acc[i][j] + s_bias[cb + j];
    }
    __syncthreads();

    // per-row MoE epilogue
    if (t < 16) {
        const float* L = s_l + t * 65;
        float p[5];
        float gm = -1e30f;
        #pragma unroll
        for (int e = 0; e < 5; e++) gm = fmaxf(gm, L[e]);
        float gsum = 0.0f;
        #pragma unroll
        for (int e = 0; e < 5; e++) { p[e] = expf(L[e] - gm); gsum += p[e]; }
        const float ginv = 1.0f / gsum;
        #pragma unroll
        for (int e = 0; e < 5; e++) p[e] *= ginv;

        int idx[5] = {0, 1, 2, 3, 4};
        #pragma unroll
        for (int a = 0; a < 3; a++) {
            int best = a;
            #pragma unroll
            for (int q = a + 1; q < 5; q++)
                if (p[idx[q]] > p[idx[best]]) best = q;
            const int tmp = idx[a]; idx[a] = idx[best]; idx[best] = tmp;
        }

        float comb[10];
        #pragma unroll
        for (int c = 0; c < 10; c++) {
            float v = 0.0f;
            #pragma unroll
            for (int k = 0; k < 3; k++)
                v = fmaf(p[idx[k]], L[5 + idx[k] * 10 + c], v);
            comb[c] = v;
        }
        float cm = -1e30f;
        #pragma unroll
        for (int c = 0; c < 10; c++) cm = fmaxf(cm, comb[c]);
        float cs = 0.0f;
        float ex[10];
        #pragma unroll
        for (int c = 0; c < 10; c++) { ex[c] = expf(comb[c] - cm); cs += ex[c]; }
        const float inv = 1.0f / cs;
        float* o = out + (row0 + t) * 10;
        #pragma unroll
        for (int c = 0; c < 10; c++) o[c] = ex[c] * inv;
    }
}

// ==================== launcher ====================
extern "C" void kernel_launch(void* const* d_in, const int* in_sizes, int n_in,
                              void* d_out, int out_size) {
    const float* x  = (const float*)d_in[0];
    const float* w1 = (const float*)d_in[1];
    const float* b1 = (const float*)d_in[2];
    const float* w2 = (const float*)d_in[3];
    const float* b2 = (const float*)d_in[4];
    const float* gw = (const float*)d_in[5];
    const float* gb = (const float*)d_in[6];
    const float* ew = (const float*)d_in[7];
    const float* eb = (const float*)d_in[8];
    float* out = (float*)d_out;

    cudaFuncSetAttribute(conv_mma_kernel,
                         cudaFuncAttributeMaxDynamicSharedMemorySize, SM_TOTAL);

    pack_weights_kernel<<<(1600 * 64 + 255) / 256, 256>>>(gw, ew);
    prep_w2t_kernel<<<(64 * WTS + 255) / 256, 256>>>(w2);
    conv_mma_kernel<<<B, 256, SM_TOTAL>>>(x, w1, b1, b2);
    moe_head_kernel<<<B / 16, 256>>>(gb, eb, out);
}

// round 12
// speedup vs baseline: 2.1686x; 2.1686x over previous
#include <cuda_runtime.h>
#include <cuda_bf16.h>
#include <math.h>
#include <cstdint>

#define B 8192

typedef unsigned long long ull;

// ---------------- packed f32x2 helpers ----------------
__device__ __forceinline__ ull pack2(float v) {
    ull r; asm("mov.b64 %0, {%1, %1};" : "=l"(r) : "f"(v)); return r;
}
__device__ __forceinline__ void fma2(ull& d, ull a, ull b) {
    asm("fma.rn.f32x2 %0, %1, %2, %0;" : "+l"(d) : "l"(a), "l"(b));
}
__device__ __forceinline__ float2 unpack2(ull v) {
    float2 f; asm("mov.b64 {%0, %1}, %2;" : "=f"(f.x), "=f"(f.y) : "l"(v)); return f;
}

// ---------------- bf16 pack helpers ----------------
__device__ __forceinline__ uint32_t bfpack(float lo, float hi) {
    uint32_t r;
    asm("cvt.rn.bf16x2.f32 %0, %1, %2;" : "=r"(r) : "f"(hi), "f"(lo));
    return r;
}

// ---------------- mma.sync m16n8k16 bf16 ----------------
__device__ __forceinline__ void mma_bf16(float* c, const uint32_t* a, const uint32_t* b) {
    asm volatile(
        "mma.sync.aligned.m16n8k16.row.col.f32.bf16.bf16.f32 "
        "{%0,%1,%2,%3}, {%4,%5,%6,%7}, {%8,%9}, {%0,%1,%2,%3};"
        : "+f"(c[0]), "+f"(c[1]), "+f"(c[2]), "+f"(c[3])
        : "r"(a[0]), "r"(a[1]), "r"(a[2]), "r"(a[3]), "r"(b[0]), "r"(b[1]));
}

// ---------------- global scratch ----------------
__device__ float g_feat[B * 1600];
__device__ float g_wpack[1600 * 56];
// B fragments: [ks 0..17][nt 0..7][lane 0..31] x {bh0, bh1, bl0, bl1}
__device__ __align__(16) uint32_t g_wfrag[18 * 8 * 32 * 4];

// ==================== prep kernels ====================
__global__ void pack_weights_kernel(const float* __restrict__ gw,
                                    const float* __restrict__ ew) {
    int i = blockIdx.x * blockDim.x + threadIdx.x;
    if (i >= 1600 * 56) return;
    int d = i / 56, j = i - d * 56;
    float v = 0.0f;
    if (j < 5)       v = gw[d * 5 + j];
    else if (j < 55) {
        int e = (j - 5) / 10, c = (j - 5) % 10;
        v = ew[(e * 1600 + d) * 10 + c];
    }
    g_wpack[i] = v;
}

// w2 [k=288][co=64] -> per-(ks,nt,lane) mma B fragments with bf16 hi/lo split
__global__ void prep_wfrag_kernel(const float* __restrict__ w2) {
    int i = blockIdx.x * blockDim.x + threadIdx.x;
    if (i >= 18 * 8 * 32) return;
    const int ks = i >> 8;
    const int r  = i & 255;
    const int nt = r >> 5;
    const int lane = r & 31;
    const int g  = lane >> 2;
    const int tq = lane & 3;
    const int co = nt * 8 + g;
    const int k0 = ks * 16 + 2 * tq;       // bh0: k0, k0+1
    const int k1 = k0 + 8;                 // bh1: k1, k1+1

    float v00 = w2[k0 * 64 + co],       v01 = w2[(k0 + 1) * 64 + co];
    float v10 = w2[k1 * 64 + co],       v11 = w2[(k1 + 1) * 64 + co];
    float h00 = __bfloat162float(__float2bfloat16_rn(v00));
    float h01 = __bfloat162float(__float2bfloat16_rn(v01));
    float h10 = __bfloat162float(__float2bfloat16_rn(v10));
    float h11 = __bfloat162float(__float2bfloat16_rn(v11));

    uint32_t* o = g_wfrag + (size_t)i * 4;
    o[0] = bfpack(h00, h01);
    o[1] = bfpack(h10, h11);
    o[2] = bfpack(v00 - h00, v01 - h01);
    o[3] = bfpack(v10 - h10, v11 - h11);
}

// ==================== K1: conv1(FFMA2) + conv2(mma.sync, warp=mtile) ====================
// smem (bytes), all 16B-aligned:
#define SM_HH  0                       // [169][17] u32 hi pairs = 11492 -> 11504
#define SM_HL  11504                   // lo pairs
#define SM_WF  23008                   // 18*8*32*4 u32 = 73728
#define SM_X   96736                   // 784 f32
#define SM_W1  99872                   // 288 f32
#define SM_B1  101024
#define SM_B2  101152
#define SM_TOTAL 101440
#define SM_D   SM_WF                   // D [112][66] f32 = 29568, aliases WF after mainloop
#define HST 17                         // u32 stride per h1 cell

__global__ __launch_bounds__(256, 2) void conv_mma_kernel(
    const float* __restrict__ x,
    const float* __restrict__ w1,
    const float* __restrict__ b1,
    const float* __restrict__ b2)
{
    extern __shared__ char smc[];
    uint32_t* s_hh = (uint32_t*)(smc + SM_HH);
    uint32_t* s_hl = (uint32_t*)(smc + SM_HL);
    const uint4* s_wf = (const uint4*)(smc + SM_WF);
    float* s_x  = (float*)(smc + SM_X);
    float* s_w1 = (float*)(smc + SM_W1);
    float* s_b1 = (float*)(smc + SM_B1);
    float* s_b2 = (float*)(smc + SM_B2);
    float* s_D  = (float*)(smc + SM_D);

    const int t    = threadIdx.x;
    const int wid  = t >> 5;
    const int lane = t & 31;
    const int bb   = blockIdx.x;

    // ---- stage x, w1, biases, B fragments ----
    {
        const float* xi = x + bb * 784;
        for (int i = t; i < 784; i += 256) s_x[i] = xi[i];
        for (int i = t; i < 288; i += 256) s_w1[i] = w1[i];
        if (t < 32) s_b1[t] = b1[t];
        else if (t < 96) s_b2[t - 32] = b2[t - 32];
        const float4* src = (const float4*)g_wfrag;
        float4* dst = (float4*)(smc + SM_WF);
        for (int i = t; i < 4608; i += 256) dst[i] = src[i];
    }
    __syncthreads();

    // ---- conv1 + relu + pool -> s_hh/s_hl (FFMA2, bf16 split at epilogue) ----
    for (int i = t; i < 676; i += 256) {
        const int cell = i >> 2;
        const int c0   = (i & 3) * 8;
        const int qy = cell / 13, qx = cell - qy * 13;
        const float* xb = s_x + (2 * qy) * 28 + 2 * qx;

        ull a1[4][4];
        #pragma unroll
        for (int p = 0; p < 4; p++)
            #pragma unroll
            for (int j = 0; j < 4; j++) a1[p][j] = 0ULL;

        #pragma unroll
        for (int ky = 0; ky < 3; ky++)
            #pragma unroll
            for (int kx = 0; kx < 3; kx++) {
                const float* xp = xb + ky * 28 + kx;
                const ull xpk[4] = { pack2(xp[0]), pack2(xp[1]), pack2(xp[28]), pack2(xp[29]) };
                const ulonglong2* wq = (const ulonglong2*)(s_w1 + (ky * 3 + kx) * 32 + c0);
                const ulonglong2 wA = wq[0], wB = wq[1];
                const ull wv[4] = { wA.x, wA.y, wB.x, wB.y };
                #pragma unroll
                for (int p = 0; p < 4; p++)
                    #pragma unroll
                    for (int j = 0; j < 4; j++) fma2(a1[p][j], xpk[p], wv[j]);
            }
        uint32_t* hh = s_hh + cell * HST + (c0 >> 1);
        uint32_t* hl = s_hl + cell * HST + (c0 >> 1);
        #pragma unroll
        for (int j = 0; j < 4; j++) {           // pair j -> co 2j, 2j+1
            const float2 u0 = unpack2(a1[0][j]), u1 = unpack2(a1[1][j]);
            const float2 u2 = unpack2(a1[2][j]), u3 = unpack2(a1[3][j]);
            const float v0 = fmaxf(fmaxf(fmaxf(u0.x, u1.x), fmaxf(u2.x, u3.x)) + s_b1[c0 + 2*j],     0.0f);
            const float v1 = fmaxf(fmaxf(fmaxf(u0.y, u1.y), fmaxf(u2.y, u3.y)) + s_b1[c0 + 2*j + 1], 0.0f);
            const float h0 = __bfloat162float(__float2bfloat16_rn(v0));
            const float h1 = __bfloat162float(__float2bfloat16_rn(v1));
            hh[j] = bfpack(h0, h1);
            hl[j] = bfpack(v0 - h0, v1 - h1);
        }
    }
    __syncthreads();

    // ---- conv2 GEMM: M=112 x N=64 x K=288; warp w (0..6) = m-tile w, all 8 n-tiles ----
    const int g  = lane >> 2;
    const int tq = lane & 3;

    float acc[8][4];
    #pragma unroll
    for (int nt = 0; nt < 8; nt++)
        #pragma unroll
        for (int q = 0; q < 4; q++) acc[nt][q] = 0.0f;

    const int r0 = wid * 16 + g;
    const int r1 = r0 + 8;
    const int crow0 = (r0 < 100) ? (r0 / 10) * 13 + (r0 % 10) : 0;
    const int crow1 = (r1 < 100) ? (r1 / 10) * 13 + (r1 % 10) : 0;

    if (wid < 7) {
        #pragma unroll 1
        for (int ks = 0; ks < 18; ks++) {
            const int tap = ks >> 1;
            const int ty = tap / 3, tx = tap - ty * 3;
            const int toff = ty * 13 + tx;
            const int j0 = ((ks & 1) << 3) + tq;      // u32 index within cell row

            // A fragments: 8 LDS.32, zero conversions
            const uint32_t* hh0 = s_hh + (crow0 + toff) * HST;
            const uint32_t* hh1 = s_hh + (crow1 + toff) * HST;
            const uint32_t* hl0 = s_hl + (crow0 + toff) * HST;
            const uint32_t* hl1 = s_hl + (crow1 + toff) * HST;
            uint32_t ah[4], al[4];
            ah[0] = hh0[j0];      ah[1] = hh1[j0];
            ah[2] = hh0[j0 + 4];  ah[3] = hh1[j0 + 4];
            al[0] = hl0[j0];      al[1] = hl1[j0];
            al[2] = hl0[j0 + 4];  al[3] = hl1[j0 + 4];

            // B fragments: one LDS.128 per n-tile
            #pragma unroll
            for (int nt = 0; nt < 8; nt++) {
                const uint4 f = s_wf[(ks * 8 + nt) * 32 + lane];
                uint32_t bh[2] = { f.x, f.y };
                uint32_t bl[2] = { f.z, f.w };
                mma_bf16(acc[nt], ah, bh);
                mma_bf16(acc[nt], al, bh);
                mma_bf16(acc[nt], ah, bl);
            }
        }
    }

    // ---- write D to smem (aliases WF -> barrier first) ----
    __syncthreads();
    if (wid < 7) {
        const int dr0 = wid * 16 + g;
        #pragma unroll
        for (int nt = 0; nt < 8; nt++) {
            const int col = nt * 8 + 2 * tq;
            *(float2*)(s_D + dr0 * 66 + col)       = make_float2(acc[nt][0], acc[nt][1]);
            *(float2*)(s_D + (dr0 + 8) * 66 + col) = make_float2(acc[nt][2], acc[nt][3]);
        }
    }
    __syncthreads();

    // ---- maxpool + bias + relu -> g_feat (rows r = y*10+x) ----
    if (t < 200) {
        const int cg = t / 25;
        const int pc = t - cg * 25;
        const int co0 = cg * 8;
        const int qy = pc / 5, qx = pc - qy * 5;
        const float* r0p = s_D + ((2 * qy) * 10 + 2 * qx) * 66 + co0;
        const float* r1p = r0p + 66;
        const float* r2p = s_D + ((2 * qy + 1) * 10 + 2 * qx) * 66 + co0;
        const float* r3p = r2p + 66;
        float* fo = g_feat + (bb * 25 + pc) * 64 + co0;
        #pragma unroll
        for (int j = 0; j < 8; j++) {
            const float m = fmaxf(fmaxf(r0p[j], r1p[j]), fmaxf(r2p[j], r3p[j]));
            fo[j] = fmaxf(m + s_b2[co0 + j], 0.0f);
        }
    }
}

// ==================== K2: head GEMM + MoE epilogue — exact R10 (measured 92us) ====================
#define KC 64
#define FS 68
#define STG (16 * FS + KC * 56)
__global__ __launch_bounds__(256) void moe_head_kernel(
    const float* __restrict__ gb,
    const float* __restrict__ eb,
    float* __restrict__ out)
{
    __shared__ float s_stage[2 * STG];
    __shared__ float s_l[16 * 57];
    __shared__ float s_bias[56];
    float* s_p = s_stage;

    const int t    = threadIdx.x;
    const int s    = t >> 6;
    const int u    = t & 63;
    const int rg   = u >> 3;
    const int cb   = (u & 7) * 7;
    const int r0   = rg * 2;
    const int row0 = blockIdx.x * 16;
    const int kk0  = s * 16;

    if (t < 56) s_bias[t] = (t < 5) ? gb[t] : eb[t - 5];

    float acc[2][7];
    #pragma unroll
    for (int i = 0; i < 2; i++)
        #pragma unroll
        for (int j = 0; j < 7; j++) acc[i][j] = 0.0f;

    auto load_stage = [&](int chunk, float* buf) {
        const int k0 = chunk * KC;
        float* sf = buf;
        float* sw = buf + 16 * FS;
        {
            const int r = t >> 4, c0 = (t & 15) * 4;
            const float4 v = *(const float4*)(g_feat + (row0 + r) * 1600 + k0 + c0);
            *(float4*)(sf + r * FS + c0) = v;
        }
        {
            const float4* src = (const float4*)(g_wpack + k0 * 56);
            float4* dst = (float4*)sw;
            for (int i = t; i < 896; i += 256) dst[i] = src[i];
        }
    };

    load_stage(0, s_stage);
    __syncthreads();

    for (int chunk = 0; chunk < 25; chunk++) {
        float* cur = s_stage + (chunk & 1) * STG;
        if (chunk < 24) load_stage(chunk + 1, s_stage + ((chunk + 1) & 1) * STG);

        const float* sf = cur;
        const float* sw = cur + 16 * FS;
        #pragma unroll 4
        for (int kk = kk0; kk < kk0 + 16; kk++) {
            const float f0 = sf[(r0    ) * FS + kk];
            const float f1 = sf[(r0 + 1) * FS + kk];
            const float* wr = sw + kk * 56 + cb;
            #pragma unroll
            for (int j = 0; j < 7; j++) {
                const float wv = wr[j];
                acc[0][j] = fmaf(f0, wv, acc[0][j]);
                acc[1][j] = fmaf(f1, wv, acc[1][j]);
            }
        }
        __syncthreads();
    }

    if (s > 0) {
        float* pp = s_p + ((s - 1) * 64 + u) * 14;
        #pragma unroll
        for (int i = 0; i < 2; i++)
            #pragma unroll
            for (int j = 0; j < 7; j++) pp[i * 7 + j] = acc[i][j];
    }
    __syncthreads();
    if (s == 0) {
        #pragma unroll
        for (int q = 0; q < 3; q++) {
            const float* pp = s_p + (q * 64 + u) * 14;
            #pragma unroll
            for (int i = 0; i < 2; i++)
                #pragma unroll
                for (int j = 0; j < 7; j++) acc[i][j] += pp[i * 7 + j];
        }
        #pragma unroll
        for (int i = 0; i < 2; i++)
            #pragma unroll
            for (int j = 0; j < 7; j++)
                s_l[(r0 + i) * 57 + cb + j] = acc[i][j] + s_bias[cb + j];
    }
    __syncthreads();

    if (t < 16) {
        const float* L = s_l + t * 57;
        float p[5];
        float gm = -1e30f;
        #pragma unroll
        for (int e = 0; e < 5; e++) gm = fmaxf(gm, L[e]);
        float gsum = 0.0f;
        #pragma unroll
        for (int e = 0; e < 5; e++) { p[e] = expf(L[e] - gm); gsum += p[e]; }
        const float ginv = 1.0f / gsum;
        #pragma unroll
        for (int e = 0; e < 5; e++) p[e] *= ginv;

        int idx[5] = {0, 1, 2, 3, 4};
        #pragma unroll
        for (int a = 0; a < 3; a++) {
            int best = a;
            #pragma unroll
            for (int q = a + 1; q < 5; q++)
                if (p[idx[q]] > p[idx[best]]) best = q;
            const int tmp = idx[a]; idx[a] = idx[best]; idx[best] = tmp;
        }

        float comb[10];
        #pragma unroll
        for (int c = 0; c < 10; c++) {
            float v = 0.0f;
            #pragma unroll
            for (int k = 0; k < 3; k++)
                v = fmaf(p[idx[k]], L[5 + idx[k] * 10 + c], v);
            comb[c] = v;
        }
        float cm = -1e30f;
        #pragma unroll
        for (int c = 0; c < 10; c++) cm = fmaxf(cm, comb[c]);
        float cs = 0.0f;
        float ex[10];
        #pragma unroll
        for (int c = 0; c < 10; c++) { ex[c] = expf(comb[c] - cm); cs += ex[c]; }
        const float inv = 1.0f / cs;
        float* o = out + (row0 + t) * 10;
        #pragma unroll
        for (int c = 0; c < 10; c++) o[c] = ex[c] * inv;
    }
}

// ==================== launcher ====================
extern "C" void kernel_launch(void* const* d_in, const int* in_sizes, int n_in,
                              void* d_out, int out_size) {
    const float* x  = (const float*)d_in[0];
    const float* w1 = (const float*)d_in[1];
    const float* b1 = (const float*)d_in[2];
    const float* w2 = (const float*)d_in[3];
    const float* b2 = (const float*)d_in[4];
    const float* gw = (const float*)d_in[5];
    const float* gb = (const float*)d_in[6];
    const float* ew = (const float*)d_in[7];
    const float* eb = (const float*)d_in[8];
    float* out = (float*)d_out;

    cudaFuncSetAttribute(conv_mma_kernel,
                         cudaFuncAttributeMaxDynamicSharedMemorySize, SM_TOTAL);

    pack_weights_kernel<<<(1600 * 56 + 255) / 256, 256>>>(gw, ew);
    prep_wfrag_kernel<<<(18 * 8 * 32 + 255) / 256, 256>>>(w2);
    conv_mma_kernel<<<B, 256, SM_TOTAL>>>(x, w1, b1, b2);
    moe_head_kernel<<<B / 16, 256>>>(gb, eb, out);
}

// round 13
// speedup vs baseline: 2.6662x; 1.2294x over previous
#include <cuda_runtime.h>
#include <cuda_fp16.h>
#include <math.h>
#include <cstdint>

#define B 8192

typedef unsigned long long ull;

// ---------------- packed f32x2 helpers ----------------
__device__ __forceinline__ ull pack2(float v) {
    ull r; asm("mov.b64 %0, {%1, %1};" : "=l"(r) : "f"(v)); return r;
}
__device__ __forceinline__ void fma2(ull& d, ull a, ull b) {
    asm("fma.rn.f32x2 %0, %1, %2, %0;" : "+l"(d) : "l"(a), "l"(b));
}
__device__ __forceinline__ float2 unpack2(ull v) {
    float2 f; asm("mov.b64 {%0, %1}, %2;" : "=f"(f.x), "=f"(f.y) : "l"(v)); return f;
}

// ---------------- fp16 pack helper: u32 = {lo half: h(v0), hi half: h(v1)} ----------------
__device__ __forceinline__ uint32_t hpack(float v0, float v1) {
    __half2 h = __floats2half2_rn(v0, v1);
    return *(uint32_t*)&h;
}

// ---------------- mma.sync m16n8k16 fp16 (f32 acc) ----------------
__device__ __forceinline__ void mma_fp16(float* c, const uint32_t* a, const uint32_t* b) {
    asm volatile(
        "mma.sync.aligned.m16n8k16.row.col.f32.f16.f16.f32 "
        "{%0,%1,%2,%3}, {%4,%5,%6,%7}, {%8,%9}, {%0,%1,%2,%3};"
        : "+f"(c[0]), "+f"(c[1]), "+f"(c[2]), "+f"(c[3])
        : "r"(a[0]), "r"(a[1]), "r"(a[2]), "r"(a[3]), "r"(b[0]), "r"(b[1]));
}

// ---------------- global scratch ----------------
__device__ float g_feat[B * 1600];
__device__ float g_wpack[1600 * 56];
// B fragments (fp16, single image): [ks 0..17][nt 0..7][lane 0..31] x {b0, b1}
__device__ __align__(16) uint32_t g_wfrag[18 * 8 * 32 * 2];

// ==================== prep kernels ====================
__global__ void pack_weights_kernel(const float* __restrict__ gw,
                                    const float* __restrict__ ew) {
    int i = blockIdx.x * blockDim.x + threadIdx.x;
    if (i >= 1600 * 56) return;
    int d = i / 56, j = i - d * 56;
    float v = 0.0f;
    if (j < 5)       v = gw[d * 5 + j];
    else if (j < 55) {
        int e = (j - 5) / 10, c = (j - 5) % 10;
        v = ew[(e * 1600 + d) * 10 + c];
    }
    g_wpack[i] = v;
}

// w2 [k=288][co=64] -> per-(ks,nt,lane) fp16 mma B fragments
__global__ void prep_wfrag_kernel(const float* __restrict__ w2) {
    int i = blockIdx.x * blockDim.x + threadIdx.x;
    if (i >= 18 * 8 * 32) return;
    const int ks = i >> 8;
    const int r  = i & 255;
    const int nt = r >> 5;
    const int lane = r & 31;
    const int g  = lane >> 2;
    const int tq = lane & 3;
    const int co = nt * 8 + g;
    const int k0 = ks * 16 + 2 * tq;       // b0: k0, k0+1
    const int k1 = k0 + 8;                 // b1: k1, k1+1

    uint32_t* o = g_wfrag + (size_t)i * 2;
    o[0] = hpack(w2[k0 * 64 + co], w2[(k0 + 1) * 64 + co]);
    o[1] = hpack(w2[k1 * 64 + co], w2[(k1 + 1) * 64 + co]);
}

// ==================== K1: conv1(FFMA2) + conv2(mma.sync fp16 2-term) ====================
// smem (bytes), all 16B-aligned:
#define SM_HH  0                       // [169][17] u32 hi pairs -> 11504
#define SM_HL  11504                   // lo pairs
#define SM_WF  23008                   // 18*8*32*2 u32 = 36864
#define SM_X   59872                   // 784 f32
#define SM_W1  63008                   // 288 f32
#define SM_B1  64160
#define SM_B2  64288
#define SM_TOTAL 64576
#define SM_D   SM_WF                   // D [112][66] f32 = 29568 <= 36864, aliases WF
#define HST 17                         // u32 stride per h1 cell

__global__ __launch_bounds__(256, 2) void conv_mma_kernel(
    const float* __restrict__ x,
    const float* __restrict__ w1,
    const float* __restrict__ b1,
    const float* __restrict__ b2)
{
    extern __shared__ char smc[];
    uint32_t* s_hh = (uint32_t*)(smc + SM_HH);
    uint32_t* s_hl = (uint32_t*)(smc + SM_HL);
    const uint2* s_wf = (const uint2*)(smc + SM_WF);
    float* s_x  = (float*)(smc + SM_X);
    float* s_w1 = (float*)(smc + SM_W1);
    float* s_b1 = (float*)(smc + SM_B1);
    float* s_b2 = (float*)(smc + SM_B2);
    float* s_D  = (float*)(smc + SM_D);

    const int t    = threadIdx.x;
    const int wid  = t >> 5;
    const int lane = t & 31;
    const int bb   = blockIdx.x;

    // ---- stage x, w1, biases, B fragments ----
    {
        const float* xi = x + bb * 784;
        for (int i = t; i < 784; i += 256) s_x[i] = xi[i];
        for (int i = t; i < 288; i += 256) s_w1[i] = w1[i];
        if (t < 32) s_b1[t] = b1[t];
        else if (t < 96) s_b2[t - 32] = b2[t - 32];
        const float4* src = (const float4*)g_wfrag;
        float4* dst = (float4*)(smc + SM_WF);
        for (int i = t; i < 2304; i += 256) dst[i] = src[i];
    }
    __syncthreads();

    // ---- conv1 + relu + pool -> s_hh/s_hl (FFMA2, fp16 split at epilogue) ----
    for (int i = t; i < 676; i += 256) {
        const int cell = i >> 2;
        const int c0   = (i & 3) * 8;
        const int qy = cell / 13, qx = cell - qy * 13;
        const float* xb = s_x + (2 * qy) * 28 + 2 * qx;

        ull a1[4][4];
        #pragma unroll
        for (int p = 0; p < 4; p++)
            #pragma unroll
            for (int j = 0; j < 4; j++) a1[p][j] = 0ULL;

        #pragma unroll
        for (int ky = 0; ky < 3; ky++)
            #pragma unroll
            for (int kx = 0; kx < 3; kx++) {
                const float* xp = xb + ky * 28 + kx;
                const ull xpk[4] = { pack2(xp[0]), pack2(xp[1]), pack2(xp[28]), pack2(xp[29]) };
                const ulonglong2* wq = (const ulonglong2*)(s_w1 + (ky * 3 + kx) * 32 + c0);
                const ulonglong2 wA = wq[0], wB = wq[1];
                const ull wv[4] = { wA.x, wA.y, wB.x, wB.y };
                #pragma unroll
                for (int p = 0; p < 4; p++)
                    #pragma unroll
                    for (int j = 0; j < 4; j++) fma2(a1[p][j], xpk[p], wv[j]);
            }
        uint32_t* hh = s_hh + cell * HST + (c0 >> 1);
        uint32_t* hl = s_hl + cell * HST + (c0 >> 1);
        #pragma unroll
        for (int j = 0; j < 4; j++) {           // pair j -> co 2j, 2j+1
            const float2 u0 = unpack2(a1[0][j]), u1 = unpack2(a1[1][j]);
            const float2 u2 = unpack2(a1[2][j]), u3 = unpack2(a1[3][j]);
            const float v0 = fmaxf(fmaxf(fmaxf(u0.x, u1.x), fmaxf(u2.x, u3.x)) + s_b1[c0 + 2*j],     0.0f);
            const float v1 = fmaxf(fmaxf(fmaxf(u0.y, u1.y), fmaxf(u2.y, u3.y)) + s_b1[c0 + 2*j + 1], 0.0f);
            const __half h0 = __float2half_rn(v0);
            const __half h1 = __float2half_rn(v1);
            const __half2 hhv = __halves2half2(h0, h1);
            hh[j] = *(const uint32_t*)&hhv;
            hl[j] = hpack(v0 - __half2float(h0), v1 - __half2float(h1));
        }
    }
    __syncthreads();

    // ---- conv2 GEMM: M=112 x N=64 x K=288; warp w (0..6) = m-tile w, all 8 n-tiles ----
    const int g  = lane >> 2;
    const int tq = lane & 3;

    float acc[8][4];
    #pragma unroll
    for (int nt = 0; nt < 8; nt++)
        #pragma unroll
        for (int q = 0; q < 4; q++) acc[nt][q] = 0.0f;

    const int r0 = wid * 16 + g;
    const int r1 = r0 + 8;
    const int crow0 = (r0 < 100) ? (r0 / 10) * 13 + (r0 % 10) : 0;
    const int crow1 = (r1 < 100) ? (r1 / 10) * 13 + (r1 % 10) : 0;

    if (wid < 7) {
        #pragma unroll 1
        for (int ks = 0; ks < 18; ks++) {
            const int tap = ks >> 1;
            const int ty = tap / 3, tx = tap - ty * 3;
            const int toff = ty * 13 + tx;
            const int j0 = ((ks & 1) << 3) + tq;      // u32 index within cell row

            // A fragments: 8 LDS.32, zero conversions
            const uint32_t* hh0 = s_hh + (crow0 + toff) * HST;
            const uint32_t* hh1 = s_hh + (crow1 + toff) * HST;
            const uint32_t* hl0 = s_hl + (crow0 + toff) * HST;
            const uint32_t* hl1 = s_hl + (crow1 + toff) * HST;
            uint32_t ah[4], al[4];
            ah[0] = hh0[j0];      ah[1] = hh1[j0];
            ah[2] = hh0[j0 + 4];  ah[3] = hh1[j0 + 4];
            al[0] = hl0[j0];      al[1] = hl1[j0];
            al[2] = hl0[j0 + 4];  al[3] = hl1[j0 + 4];

            // B fragments: one LDS.64 per n-tile; 2 MMAs per n-tile
            #pragma unroll
            for (int nt = 0; nt < 8; nt++) {
                const uint2 f = s_wf[(ks * 8 + nt) * 32 + lane];
                uint32_t bfr[2] = { f.x, f.y };
                mma_fp16(acc[nt], ah, bfr);
                mma_fp16(acc[nt], al, bfr);
            }
        }
    }

    // ---- write D to smem (aliases WF -> barrier first) ----
    __syncthreads();
    if (wid < 7) {
        const int dr0 = wid * 16 + g;
        #pragma unroll
        for (int nt = 0; nt < 8; nt++) {
            const int col = nt * 8 + 2 * tq;
            *(float2*)(s_D + dr0 * 66 + col)       = make_float2(acc[nt][0], acc[nt][1]);
            *(float2*)(s_D + (dr0 + 8) * 66 + col) = make_float2(acc[nt][2], acc[nt][3]);
        }
    }
    __syncthreads();

    // ---- maxpool + bias + relu -> g_feat (rows r = y*10+x) ----
    if (t < 200) {
        const int cg = t / 25;
        const int pc = t - cg * 25;
        const int co0 = cg * 8;
        const int qy = pc / 5, qx = pc - qy * 5;
        const float* r0p = s_D + ((2 * qy) * 10 + 2 * qx) * 66 + co0;
        const float* r1p = r0p + 66;
        const float* r2p = s_D + ((2 * qy + 1) * 10 + 2 * qx) * 66 + co0;
        const float* r3p = r2p + 66;
        float* fo = g_feat + (bb * 25 + pc) * 64 + co0;
        #pragma unroll
        for (int j = 0; j < 8; j++) {
            const float m = fmaxf(fmaxf(r0p[j], r1p[j]), fmaxf(r2p[j], r3p[j]));
            fo[j] = fmaxf(m + s_b2[co0 + j], 0.0f);
        }
    }
}

// ==================== K2: head GEMM + MoE epilogue — exact R10/R12 (measured 92us) ====================
#define KC 64
#define FS 68
#define STG (16 * FS + KC * 56)
__global__ __launch_bounds__(256) void moe_head_kernel(
    const float* __restrict__ gb,
    const float* __restrict__ eb,
    float* __restrict__ out)
{
    __shared__ float s_stage[2 * STG];
    __shared__ float s_l[16 * 57];
    __shared__ float s_bias[56];
    float* s_p = s_stage;

    const int t    = threadIdx.x;
    const int s    = t >> 6;
    const int u    = t & 63;
    const int rg   = u >> 3;
    const int cb   = (u & 7) * 7;
    const int r0   = rg * 2;
    const int row0 = blockIdx.x * 16;
    const int kk0  = s * 16;

    if (t < 56) s_bias[t] = (t < 5) ? gb[t] : eb[t - 5];

    float acc[2][7];
    #pragma unroll
    for (int i = 0; i < 2; i++)
        #pragma unroll
        for (int j = 0; j < 7; j++) acc[i][j] = 0.0f;

    auto load_stage = [&](int chunk, float* buf) {
        const int k0 = chunk * KC;
        float* sf = buf;
        float* sw = buf + 16 * FS;
        {
            const int r = t >> 4, c0 = (t & 15) * 4;
            const float4 v = *(const float4*)(g_feat + (row0 + r) * 1600 + k0 + c0);
            *(float4*)(sf + r * FS + c0) = v;
        }
        {
            const float4* src = (const float4*)(g_wpack + k0 * 56);
            float4* dst = (float4*)sw;
            for (int i = t; i < 896; i += 256) dst[i] = src[i];
        }
    };

    load_stage(0, s_stage);
    __syncthreads();

    for (int chunk = 0; chunk < 25; chunk++) {
        float* cur = s_stage + (chunk & 1) * STG;
        if (chunk < 24) load_stage(chunk + 1, s_stage + ((chunk + 1) & 1) * STG);

        const float* sf = cur;
        const float* sw = cur + 16 * FS;
        #pragma unroll 4
        for (int kk = kk0; kk < kk0 + 16; kk++) {
            const float f0 = sf[(r0    ) * FS + kk];
            const float f1 = sf[(r0 + 1) * FS + kk];
            const float* wr = sw + kk * 56 + cb;
            #pragma unroll
            for (int j = 0; j < 7; j++) {
                const float wv = wr[j];
                acc[0][j] = fmaf(f0, wv, acc[0][j]);
                acc[1][j] = fmaf(f1, wv, acc[1][j]);
            }
        }
        __syncthreads();
    }

    if (s > 0) {
        float* pp = s_p + ((s - 1) * 64 + u) * 14;
        #pragma unroll
        for (int i = 0; i < 2; i++)
            #pragma unroll
            for (int j = 0; j < 7; j++) pp[i * 7 + j] = acc[i][j];
    }
    __syncthreads();
    if (s == 0) {
        #pragma unroll
        for (int q = 0; q < 3; q++) {
            const float* pp = s_p + (q * 64 + u) * 14;
            #pragma unroll
            for (int i = 0; i < 2; i++)
                #pragma unroll
                for (int j = 0; j < 7; j++) acc[i][j] += pp[i * 7 + j];
        }
        #pragma unroll
        for (int i = 0; i < 2; i++)
            #pragma unroll
            for (int j = 0; j < 7; j++)
                s_l[(r0 + i) * 57 + cb + j] = acc[i][j] + s_bias[cb + j];
    }
    __syncthreads();

    if (t < 16) {
        const float* L = s_l + t * 57;
        float p[5];
        float gm = -1e30f;
        #pragma unroll
        for (int e = 0; e < 5; e++) gm = fmaxf(gm, L[e]);
        float gsum = 0.0f;
        #pragma unroll
        for (int e = 0; e < 5; e++) { p[e] = expf(L[e] - gm); gsum += p[e]; }
        const float ginv = 1.0f / gsum;
        #pragma unroll
        for (int e = 0; e < 5; e++) p[e] *= ginv;

        int idx[5] = {0, 1, 2, 3, 4};
        #pragma unroll
        for (int a = 0; a < 3; a++) {
            int best = a;
            #pragma unroll
            for (int q = a + 1; q < 5; q++)
                if (p[idx[q]] > p[idx[best]]) best = q;
            const int tmp = idx[a]; idx[a] = idx[best]; idx[best] = tmp;
        }

        float comb[10];
        #pragma unroll
        for (int c = 0; c < 10; c++) {
            float v = 0.0f;
            #pragma unroll
            for (int k = 0; k < 3; k++)
                v = fmaf(p[idx[k]], L[5 + idx[k] * 10 + c], v);
            comb[c] = v;
        }
        float cm = -1e30f;
        #pragma unroll
        for (int c = 0; c < 10; c++) cm = fmaxf(cm, comb[c]);
        float cs = 0.0f;
        float ex[10];
        #pragma unroll
        for (int c = 0; c < 10; c++) { ex[c] = expf(comb[c] - cm); cs += ex[c]; }
        const float inv = 1.0f / cs;
        float* o = out + (row0 + t) * 10;
        #pragma unroll
        for (int c = 0; c < 10; c++) o[c] = ex[c] * inv;
    }
}

// ==================== launcher ====================
extern "C" void kernel_launch(void* const* d_in, const int* in_sizes, int n_in,
                              void* d_out, int out_size) {
    const float* x  = (const float*)d_in[0];
    const float* w1 = (const float*)d_in[1];
    const float* b1 = (const float*)d_in[2];
    const float* w2 = (const float*)d_in[3];
    const float* b2 = (const float*)d_in[4];
    const float* gw = (const float*)d_in[5];
    const float* gb = (const float*)d_in[6];
    const float* ew = (const float*)d_in[7];
    const float* eb = (const float*)d_in[8];
    float* out = (float*)d_out;

    cudaFuncSetAttribute(conv_mma_kernel,
                         cudaFuncAttributeMaxDynamicSharedMemorySize, SM_TOTAL);

    pack_weights_kernel<<<(1600 * 56 + 255) / 256, 256>>>(gw, ew);
    prep_wfrag_kernel<<<(18 * 8 * 32 + 255) / 256, 256>>>(w2);
    conv_mma_kernel<<<B, 256, SM_TOTAL>>>(x, w1, b1, b2);
    moe_head_kernel<<<B / 16, 256>>>(gb, eb, out);
}

// round 14
// speedup vs baseline: 3.5711x; 1.3394x over previous
#include <cuda_runtime.h>
#include <cuda_fp16.h>
#include <math.h>
#include <cstdint>

#define B 8192

typedef unsigned long long ull;

// ---------------- packed f32x2 helpers ----------------
__device__ __forceinline__ ull pack2(float v) {
    ull r; asm("mov.b64 %0, {%1, %1};" : "=l"(r) : "f"(v)); return r;
}
__device__ __forceinline__ void fma2(ull& d, ull a, ull b) {
    asm("fma.rn.f32x2 %0, %1, %2, %0;" : "+l"(d) : "l"(a), "l"(b));
}
__device__ __forceinline__ float2 unpack2(ull v) {
    float2 f; asm("mov.b64 {%0, %1}, %2;" : "=f"(f.x), "=f"(f.y) : "l"(v)); return f;
}

// ---------------- fp16 pack: u32 = {lo: h(v0), hi: h(v1)} ----------------
__device__ __forceinline__ uint32_t hpack(float v0, float v1) {
    __half2 h = __floats2half2_rn(v0, v1);
    return *(uint32_t*)&h;
}

// ---------------- mma.sync m16n8k16 fp16 (f32 acc) ----------------
__device__ __forceinline__ void mma_fp16(float* c, const uint32_t* a, const uint32_t* b) {
    asm volatile(
        "mma.sync.aligned.m16n8k16.row.col.f32.f16.f16.f32 "
        "{%0,%1,%2,%3}, {%4,%5,%6,%7}, {%8,%9}, {%0,%1,%2,%3};"
        : "+f"(c[0]), "+f"(c[1]), "+f"(c[2]), "+f"(c[3])
        : "r"(a[0]), "r"(a[1]), "r"(a[2]), "r"(a[3]), "r"(b[0]), "r"(b[1]));
}

// ---------------- global scratch ----------------
__device__ __align__(16) uint32_t g_fh[B * 800];   // feat fp16 hi pairs [b][800]
__device__ __align__(16) uint32_t g_fl[B * 800];   // feat fp16 lo pairs
// conv2 B fragments: [ks 0..17][nt 0..7][lane] x {b0,b1}
__device__ __align__(16) uint32_t g_wfrag[18 * 8 * 32 * 2];
// head B fragments: [ks 0..99][nt 0..6][lane] x {b0,b1}
__device__ __align__(16) uint32_t g_hfrag[100 * 7 * 32 * 2];

// ==================== prep: conv2 w fragments (fp16) ====================
__global__ void prep_wfrag_kernel(const float* __restrict__ w2) {
    int i = blockIdx.x * blockDim.x + threadIdx.x;
    if (i >= 18 * 8 * 32) return;
    const int ks = i >> 8;
    const int r  = i & 255;
    const int nt = r >> 5;
    const int lane = r & 31;
    const int g  = lane >> 2;
    const int tq = lane & 3;
    const int co = nt * 8 + g;
    const int k0 = ks * 16 + 2 * tq;
    const int k1 = k0 + 8;
    uint32_t* o = g_wfrag + (size_t)i * 2;
    o[0] = hpack(w2[k0 * 64 + co], w2[(k0 + 1) * 64 + co]);
    o[1] = hpack(w2[k1 * 64 + co], w2[(k1 + 1) * 64 + co]);
}

// ==================== prep: head w fragments (fp16, gate+experts packed cols) ====================
__device__ __forceinline__ float head_w(const float* gw, const float* ew, int d, int j) {
    if (j < 5) return gw[d * 5 + j];
    const int e = (j - 5) / 10, c = (j - 5) % 10;
    return ew[(e * 1600 + d) * 10 + c];
}
__global__ void prep_hfrag_kernel(const float* __restrict__ gw,
                                  const float* __restrict__ ew) {
    int i = blockIdx.x * blockDim.x + threadIdx.x;
    if (i >= 100 * 7 * 32) return;
    const int ks = i / 224;
    const int rr = i - ks * 224;
    const int nt = rr >> 5;
    const int lane = rr & 31;
    const int g  = lane >> 2;
    const int tq = lane & 3;
    const int col = nt * 8 + g;            // 0..55
    const int k0 = ks * 16 + 2 * tq;
    const int k1 = k0 + 8;
    uint32_t* o = g_hfrag + (size_t)i * 2;
    o[0] = hpack(head_w(gw, ew, k0, col), head_w(gw, ew, k0 + 1, col));
    o[1] = hpack(head_w(gw, ew, k1, col), head_w(gw, ew, k1 + 1, col));
}

// ==================== K1: conv1(FFMA2) + conv2(mma.sync fp16 single-term) ====================
#define SM_HH  0                       // [169][17] u32 -> 11504
#define SM_WF  11504                   // 18*8*32*2 u32 = 36864
#define SM_X   48368                   // 784 f32
#define SM_W1  51504
#define SM_B1  52656
#define SM_B2  52784
#define SM_TOTAL 53040
#define SM_D   SM_WF                   // D [112][66] f32 = 29568 <= 36864
#define HST 17

__global__ __launch_bounds__(256, 2) void conv_mma_kernel(
    const float* __restrict__ x,
    const float* __restrict__ w1,
    const float* __restrict__ b1,
    const float* __restrict__ b2)
{
    extern __shared__ char smc[];
    uint32_t* s_hh = (uint32_t*)(smc + SM_HH);
    const uint2* s_wf = (const uint2*)(smc + SM_WF);
    float* s_x  = (float*)(smc + SM_X);
    float* s_w1 = (float*)(smc + SM_W1);
    float* s_b1 = (float*)(smc + SM_B1);
    float* s_b2 = (float*)(smc + SM_B2);
    float* s_D  = (float*)(smc + SM_D);

    const int t    = threadIdx.x;
    const int wid  = t >> 5;
    const int lane = t & 31;
    const int bb   = blockIdx.x;

    // ---- stage ----
    {
        const float* xi = x + bb * 784;
        for (int i = t; i < 784; i += 256) s_x[i] = xi[i];
        for (int i = t; i < 288; i += 256) s_w1[i] = w1[i];
        if (t < 32) s_b1[t] = b1[t];
        else if (t < 96) s_b2[t - 32] = b2[t - 32];
        const float4* src = (const float4*)g_wfrag;
        float4* dst = (float4*)(smc + SM_WF);
        for (int i = t; i < 2304; i += 256) dst[i] = src[i];
    }
    __syncthreads();

    // ---- conv1 + relu + pool -> s_hh (fp16 hi only) ----
    for (int i = t; i < 676; i += 256) {
        const int cell = i >> 2;
        const int c0   = (i & 3) * 8;
        const int qy = cell / 13, qx = cell - qy * 13;
        const float* xb = s_x + (2 * qy) * 28 + 2 * qx;

        ull a1[4][4];
        #pragma unroll
        for (int p = 0; p < 4; p++)
            #pragma unroll
            for (int j = 0; j < 4; j++) a1[p][j] = 0ULL;

        #pragma unroll
        for (int ky = 0; ky < 3; ky++)
            #pragma unroll
            for (int kx = 0; kx < 3; kx++) {
                const float* xp = xb + ky * 28 + kx;
                const ull xpk[4] = { pack2(xp[0]), pack2(xp[1]), pack2(xp[28]), pack2(xp[29]) };
                const ulonglong2* wq = (const ulonglong2*)(s_w1 + (ky * 3 + kx) * 32 + c0);
                const ulonglong2 wA = wq[0], wB = wq[1];
                const ull wv[4] = { wA.x, wA.y, wB.x, wB.y };
                #pragma unroll
                for (int p = 0; p < 4; p++)
                    #pragma unroll
                    for (int j = 0; j < 4; j++) fma2(a1[p][j], xpk[p], wv[j]);
            }
        uint32_t* hh = s_hh + cell * HST + (c0 >> 1);
        #pragma unroll
        for (int j = 0; j < 4; j++) {
            const float2 u0 = unpack2(a1[0][j]), u1 = unpack2(a1[1][j]);
            const float2 u2 = unpack2(a1[2][j]), u3 = unpack2(a1[3][j]);
            const float v0 = fmaxf(fmaxf(fmaxf(u0.x, u1.x), fmaxf(u2.x, u3.x)) + s_b1[c0 + 2*j],     0.0f);
            const float v1 = fmaxf(fmaxf(fmaxf(u0.y, u1.y), fmaxf(u2.y, u3.y)) + s_b1[c0 + 2*j + 1], 0.0f);
            hh[j] = hpack(v0, v1);
        }
    }
    __syncthreads();

    // ---- conv2 GEMM: M=112 x N=64 x K=288; 1 fp16 MMA per tile ----
    const int g  = lane >> 2;
    const int tq = lane & 3;

    float acc[8][4];
    #pragma unroll
    for (int nt = 0; nt < 8; nt++)
        #pragma unroll
        for (int q = 0; q < 4; q++) acc[nt][q] = 0.0f;

    const int r0 = wid * 16 + g;
    const int r1 = r0 + 8;
    const int crow0 = (r0 < 100) ? (r0 / 10) * 13 + (r0 % 10) : 0;
    const int crow1 = (r1 < 100) ? (r1 / 10) * 13 + (r1 % 10) : 0;

    if (wid < 7) {
        #pragma unroll 1
        for (int ks = 0; ks < 18; ks++) {
            const int tap = ks >> 1;
            const int ty = tap / 3, tx = tap - ty * 3;
            const int toff = ty * 13 + tx;
            const int j0 = ((ks & 1) << 3) + tq;

            const uint32_t* hh0 = s_hh + (crow0 + toff) * HST;
            const uint32_t* hh1 = s_hh + (crow1 + toff) * HST;
            uint32_t ah[4];
            ah[0] = hh0[j0];      ah[1] = hh1[j0];
            ah[2] = hh0[j0 + 4];  ah[3] = hh1[j0 + 4];

            #pragma unroll
            for (int nt = 0; nt < 8; nt++) {
                const uint2 f = s_wf[(ks * 8 + nt) * 32 + lane];
                uint32_t bfr[2] = { f.x, f.y };
                mma_fp16(acc[nt], ah, bfr);
            }
        }
    }

    // ---- write D to smem ----
    __syncthreads();
    if (wid < 7) {
        const int dr0 = wid * 16 + g;
        #pragma unroll
        for (int nt = 0; nt < 8; nt++) {
            const int col = nt * 8 + 2 * tq;
            *(float2*)(s_D + dr0 * 66 + col)       = make_float2(acc[nt][0], acc[nt][1]);
            *(float2*)(s_D + (dr0 + 8) * 66 + col) = make_float2(acc[nt][2], acc[nt][3]);
        }
    }
    __syncthreads();

    // ---- maxpool + bias + relu -> g_fh/g_fl (fp16 hi/lo pairs) ----
    if (t < 200) {
        const int cg = t / 25;
        const int pc = t - cg * 25;
        const int co0 = cg * 8;
        const int qy = pc / 5, qx = pc - qy * 5;
        const float* r0p = s_D + ((2 * qy) * 10 + 2 * qx) * 66 + co0;
        const float* r1p = r0p + 66;
        const float* r2p = s_D + ((2 * qy + 1) * 10 + 2 * qx) * 66 + co0;
        const float* r3p = r2p + 66;
        uint32_t* fh = g_fh + bb * 800 + pc * 32 + (co0 >> 1);
        uint32_t* fl = g_fl + bb * 800 + pc * 32 + (co0 >> 1);
        #pragma unroll
        for (int j = 0; j < 8; j += 2) {
            const float v0 = fmaxf(fmaxf(fmaxf(r0p[j],   r1p[j]),   fmaxf(r2p[j],   r3p[j]))   + s_b2[co0 + j],     0.0f);
            const float v1 = fmaxf(fmaxf(fmaxf(r0p[j+1], r1p[j+1]), fmaxf(r2p[j+1], r3p[j+1])) + s_b2[co0 + j + 1], 0.0f);
            const __half h0 = __float2half_rn(v0);
            const __half h1 = __float2half_rn(v1);
            const __half2 hv = __halves2half2(h0, h1);
            fh[j >> 1] = *(const uint32_t*)&hv;
            fl[j >> 1] = hpack(v0 - __half2float(h0), v1 - __half2float(h1));
        }
    }
}

// ==================== K2: head via mma.sync — 256 blocks x 32 rows ====================
// warps: s = w>>1 (k-split 0..3, 25 ks each), mt = w&1 (m-tile of 16 rows)
// stage layout (u32): AH[32][36] = 1152 | AL 1152 | BF [4][7][32] uint2 = 1792 -> 4096 u32
#define HSTG 4096
__global__ __launch_bounds__(256) void moe_head_kernel(
    const float* __restrict__ gb,
    const float* __restrict__ eb,
    float* __restrict__ out)
{
    __shared__ uint32_t s_stage[2 * HSTG];     // 32KB
    __shared__ float s_l[32 * 57];
    __shared__ float s_bias[56];

    const int t    = threadIdx.x;
    const int wid  = t >> 5;
    const int lane = t & 31;
    const int s    = wid >> 1;
    const int mt   = wid & 1;
    const int g    = lane >> 2;
    const int tq   = lane & 3;
    const int row0 = blockIdx.x * 32;

    if (t < 56) s_bias[t] = (t < 5) ? gb[t] : eb[t - 5];

    float acc[7][4];
    #pragma unroll
    for (int nt = 0; nt < 7; nt++)
        #pragma unroll
        for (int q = 0; q < 4; q++) acc[nt][q] = 0.0f;

    // stage loader for round r
    auto load_stage = [&](int r, uint32_t* buf) {
        // A: thread -> (row = t>>3, sp = (t>>1)&3, q = t&1); one uint4 hi + one lo
        const int row = t >> 3, sp = (t >> 1) & 3, q = t & 1;
        const size_t goff = (size_t)(row0 + row) * 800 + sp * 200 + r * 8 + q * 4;
        const int soff = row * 36 + sp * 8 + q * 4;
        *(uint4*)(buf + soff)        = *(const uint4*)(g_fh + goff);
        *(uint4*)(buf + 1152 + soff) = *(const uint4*)(g_fl + goff);
        // B: [sp][nt][lane] uint2
        uint2* bd = (uint2*)(buf + 2304);
        for (int i = t; i < 896; i += 256) {
            const int sp2 = i / 224;
            const int j   = i - sp2 * 224;
            const int ks  = sp2 * 25 + r;
            bd[i] = ((const uint2*)g_hfrag)[ks * 224 + j];
        }
    };

    load_stage(0, s_stage);
    __syncthreads();

    const int ro0 = (mt * 16 + g) * 36 + s * 8;
    const int ro1 = ro0 + 8 * 36;

    for (int r = 0; r < 25; r++) {
        uint32_t* cur = s_stage + (r & 1) * HSTG;
        if (r < 24) load_stage(r + 1, s_stage + ((r + 1) & 1) * HSTG);

        const uint32_t* AH = cur;
        const uint32_t* AL = cur + 1152;
        const uint2* BF = (const uint2*)(cur + 2304);

        uint32_t ah[4], al[4];
        ah[0] = AH[ro0 + tq];      ah[1] = AH[ro1 + tq];
        ah[2] = AH[ro0 + tq + 4];  ah[3] = AH[ro1 + tq + 4];
        al[0] = AL[ro0 + tq];      al[1] = AL[ro1 + tq];
        al[2] = AL[ro0 + tq + 4];  al[3] = AL[ro1 + tq + 4];

        #pragma unroll
        for (int nt = 0; nt < 7; nt++) {
            const uint2 f = BF[s * 224 + nt * 32 + lane];
            uint32_t bfr[2] = { f.x, f.y };
            mma_fp16(acc[nt], ah, bfr);
            mma_fp16(acc[nt], al, bfr);
        }
        __syncthreads();
    }

    // ---- k-split reduction via smem (reuse stage region; last barrier covers) ----
    float* s_p = (float*)s_stage;              // 6 groups x 896 floats = 21504B <= 32KB
    if (s > 0) {
        float* pp = s_p + ((s - 1) * 2 + mt) * 896;
        #pragma unroll
        for (int nt = 0; nt < 7; nt++)
            #pragma unroll
            for (int q = 0; q < 4; q++)
                pp[(nt * 4 + q) * 32 + lane] = acc[nt][q];
    }
    __syncthreads();
    if (s == 0) {
        #pragma unroll
        for (int q3 = 0; q3 < 3; q3++) {
            const float* pp = s_p + (q3 * 2 + mt) * 896;
            #pragma unroll
            for (int nt = 0; nt < 7; nt++)
                #pragma unroll
                for (int q = 0; q < 4; q++)
                    acc[nt][q] += pp[(nt * 4 + q) * 32 + lane];
        }
        const int row = mt * 16 + g;
        #pragma unroll
        for (int nt = 0; nt < 7; nt++) {
            const int col = nt * 8 + 2 * tq;
            s_l[row * 57 + col]           = acc[nt][0] + s_bias[col];
            s_l[row * 57 + col + 1]       = acc[nt][1] + s_bias[col + 1];
            s_l[(row + 8) * 57 + col]     = acc[nt][2] + s_bias[col];
            s_l[(row + 8) * 57 + col + 1] = acc[nt][3] + s_bias[col + 1];
        }
    }
    __syncthreads();

    // ---- per-row MoE epilogue ----
    if (t < 32) {
        const float* L = s_l + t * 57;
        float p[5];
        float gm = -1e30f;
        #pragma unroll
        for (int e = 0; e < 5; e++) gm = fmaxf(gm, L[e]);
        float gsum = 0.0f;
        #pragma unroll
        for (int e = 0; e < 5; e++) { p[e] = expf(L[e] - gm); gsum += p[e]; }
        const float ginv = 1.0f / gsum;
        #pragma unroll
        for (int e = 0; e < 5; e++) p[e] *= ginv;

        int idx[5] = {0, 1, 2, 3, 4};
        #pragma unroll
        for (int a = 0; a < 3; a++) {
            int best = a;
            #pragma unroll
            for (int q = a + 1; q < 5; q++)
                if (p[idx[q]] > p[idx[best]]) best = q;
            const int tmp = idx[a]; idx[a] = idx[best]; idx[best] = tmp;
        }

        float comb[10];
        #pragma unroll
        for (int c = 0; c < 10; c++) {
            float v = 0.0f;
            #pragma unroll
            for (int k = 0; k < 3; k++)
                v = fmaf(p[idx[k]], L[5 + idx[k] * 10 + c], v);
            comb[c] = v;
        }
        float cm = -1e30f;
        #pragma unroll
        for (int c = 0; c < 10; c++) cm = fmaxf(cm, comb[c]);
        float cs = 0.0f;
        float ex[10];
        #pragma unroll
        for (int c = 0; c < 10; c++) { ex[c] = expf(comb[c] - cm); cs += ex[c]; }
        const float inv = 1.0f / cs;
        float* o = out + (row0 + t) * 10;
        #pragma unroll
        for (int c = 0; c < 10; c++) o[c] = ex[c] * inv;
    }
}

// ==================== launcher ====================
extern "C" void kernel_launch(void* const* d_in, const int* in_sizes, int n_in,
                              void* d_out, int out_size) {
    const float* x  = (const float*)d_in[0];
    const float* w1 = (const float*)d_in[1];
    const float* b1 = (const float*)d_in[2];
    const float* w2 = (const float*)d_in[3];
    const float* b2 = (const float*)d_in[4];
    const float* gw = (const float*)d_in[5];
    const float* gb = (const float*)d_in[6];
    const float* ew = (const float*)d_in[7];
    const float* eb = (const float*)d_in[8];
    float* out = (float*)d_out;

    cudaFuncSetAttribute(conv_mma_kernel,
                         cudaFuncAttributeMaxDynamicSharedMemorySize, SM_TOTAL);

    prep_wfrag_kernel<<<(18 * 8 * 32 + 255) / 256, 256>>>(w2);
    prep_hfrag_kernel<<<(100 * 7 * 32 + 255) / 256, 256>>>(gw, ew);
    conv_mma_kernel<<<B, 256, SM_TOTAL>>>(x, w1, b1, b2);
    moe_head_kernel<<<B / 32, 256>>>(gb, eb, out);
}

// round 15
// speedup vs baseline: 3.7844x; 1.0597x over previous
#include <cuda_runtime.h>
#include <cuda_fp16.h>
#include <math.h>
#include <cstdint>

#define B 8192

typedef unsigned long long ull;

// ---------------- packed f32x2 helpers ----------------
__device__ __forceinline__ ull pack2(float v) {
    ull r; asm("mov.b64 %0, {%1, %1};" : "=l"(r) : "f"(v)); return r;
}
__device__ __forceinline__ void fma2(ull& d, ull a, ull b) {
    asm("fma.rn.f32x2 %0, %1, %2, %0;" : "+l"(d) : "l"(a), "l"(b));
}
__device__ __forceinline__ float2 unpack2(ull v) {
    float2 f; asm("mov.b64 {%0, %1}, %2;" : "=f"(f.x), "=f"(f.y) : "l"(v)); return f;
}

// ---------------- fp16 pack: u32 = {lo: h(v0), hi: h(v1)} ----------------
__device__ __forceinline__ uint32_t hpack(float v0, float v1) {
    __half2 h = __floats2half2_rn(v0, v1);
    return *(uint32_t*)&h;
}

// ---------------- mma.sync m16n8k16 fp16 (f32 acc) ----------------
__device__ __forceinline__ void mma_fp16(float* c, const uint32_t* a, const uint32_t* b) {
    asm volatile(
        "mma.sync.aligned.m16n8k16.row.col.f32.f16.f16.f32 "
        "{%0,%1,%2,%3}, {%4,%5,%6,%7}, {%8,%9}, {%0,%1,%2,%3};"
        : "+f"(c[0]), "+f"(c[1]), "+f"(c[2]), "+f"(c[3])
        : "r"(a[0]), "r"(a[1]), "r"(a[2]), "r"(a[3]), "r"(b[0]), "r"(b[1]));
}

// ---------------- global scratch ----------------
__device__ __align__(16) uint32_t g_fh[B * 800];   // feat fp16 hi pairs [b][800]
__device__ __align__(16) uint32_t g_fl[B * 800];   // feat fp16 lo pairs
__device__ __align__(16) uint32_t g_wfrag[18 * 8 * 32 * 2];    // conv2 B frags
__device__ __align__(16) uint32_t g_hfrag[100 * 7 * 32 * 2];   // head B frags

// ==================== prep: conv2 w fragments (fp16) ====================
__global__ void prep_wfrag_kernel(const float* __restrict__ w2) {
    int i = blockIdx.x * blockDim.x + threadIdx.x;
    if (i >= 18 * 8 * 32) return;
    const int ks = i >> 8;
    const int r  = i & 255;
    const int nt = r >> 5;
    const int lane = r & 31;
    const int g  = lane >> 2;
    const int tq = lane & 3;
    const int co = nt * 8 + g;
    const int k0 = ks * 16 + 2 * tq;
    const int k1 = k0 + 8;
    uint32_t* o = g_wfrag + (size_t)i * 2;
    o[0] = hpack(w2[k0 * 64 + co], w2[(k0 + 1) * 64 + co]);
    o[1] = hpack(w2[k1 * 64 + co], w2[(k1 + 1) * 64 + co]);
}

// ==================== prep: head w fragments ====================
__device__ __forceinline__ float head_w(const float* gw, const float* ew, int d, int j) {
    if (j < 5) return gw[d * 5 + j];
    const int e = (j - 5) / 10, c = (j - 5) % 10;
    return ew[(e * 1600 + d) * 10 + c];
}
__global__ void prep_hfrag_kernel(const float* __restrict__ gw,
                                  const float* __restrict__ ew) {
    int i = blockIdx.x * blockDim.x + threadIdx.x;
    if (i >= 100 * 7 * 32) return;
    const int ks = i / 224;
    const int rr = i - ks * 224;
    const int nt = rr >> 5;
    const int lane = rr & 31;
    const int g  = lane >> 2;
    const int tq = lane & 3;
    const int col = nt * 8 + g;
    const int k0 = ks * 16 + 2 * tq;
    const int k1 = k0 + 8;
    uint32_t* o = g_hfrag + (size_t)i * 2;
    o[0] = hpack(head_w(gw, ew, k0, col), head_w(gw, ew, k0 + 1, col));
    o[1] = hpack(head_w(gw, ew, k1, col), head_w(gw, ew, k1 + 1, col));
}

// ==================== K1: conv1(FFMA2) + conv2(mma.sync fp16) — 3 blocks/SM ====================
#define SM_HH  0
#define SM_WF  11504
#define SM_X   48368
#define SM_W1  51504
#define SM_B1  52656
#define SM_B2  52784
#define SM_TOTAL 53040
#define SM_D   SM_WF
#define HST 17

__global__ __launch_bounds__(256, 3) void conv_mma_kernel(
    const float* __restrict__ x,
    const float* __restrict__ w1,
    const float* __restrict__ b1,
    const float* __restrict__ b2)
{
    extern __shared__ char smc[];
    uint32_t* s_hh = (uint32_t*)(smc + SM_HH);
    const uint2* s_wf = (const uint2*)(smc + SM_WF);
    float* s_x  = (float*)(smc + SM_X);
    float* s_w1 = (float*)(smc + SM_W1);
    float* s_b1 = (float*)(smc + SM_B1);
    float* s_b2 = (float*)(smc + SM_B2);
    float* s_D  = (float*)(smc + SM_D);

    const int t    = threadIdx.x;
    const int wid  = t >> 5;
    const int lane = t & 31;
    const int bb   = blockIdx.x;

    // ---- stage ----
    {
        const float* xi = x + bb * 784;
        for (int i = t; i < 784; i += 256) s_x[i] = xi[i];
        for (int i = t; i < 288; i += 256) s_w1[i] = w1[i];
        if (t < 32) s_b1[t] = b1[t];
        else if (t < 96) s_b2[t - 32] = b2[t - 32];
        const float4* src = (const float4*)g_wfrag;
        float4* dst = (float4*)(smc + SM_WF);
        for (int i = t; i < 2304; i += 256) dst[i] = src[i];
    }
    __syncthreads();

    // ---- conv1 + relu + pool -> s_hh (fp16 hi) ----
    for (int i = t; i < 676; i += 256) {
        const int cell = i >> 2;
        const int c0   = (i & 3) * 8;
        const int qy = cell / 13, qx = cell - qy * 13;
        const float* xb = s_x + (2 * qy) * 28 + 2 * qx;

        ull a1[4][4];
        #pragma unroll
        for (int p = 0; p < 4; p++)
            #pragma unroll
            for (int j = 0; j < 4; j++) a1[p][j] = 0ULL;

        #pragma unroll
        for (int ky = 0; ky < 3; ky++)
            #pragma unroll
            for (int kx = 0; kx < 3; kx++) {
                const float* xp = xb + ky * 28 + kx;
                const ull xpk[4] = { pack2(xp[0]), pack2(xp[1]), pack2(xp[28]), pack2(xp[29]) };
                const ulonglong2* wq = (const ulonglong2*)(s_w1 + (ky * 3 + kx) * 32 + c0);
                const ulonglong2 wA = wq[0], wB = wq[1];
                const ull wv[4] = { wA.x, wA.y, wB.x, wB.y };
                #pragma unroll
                for (int p = 0; p < 4; p++)
                    #pragma unroll
                    for (int j = 0; j < 4; j++) fma2(a1[p][j], xpk[p], wv[j]);
            }
        uint32_t* hh = s_hh + cell * HST + (c0 >> 1);
        #pragma unroll
        for (int j = 0; j < 4; j++) {
            const float2 u0 = unpack2(a1[0][j]), u1 = unpack2(a1[1][j]);
            const float2 u2 = unpack2(a1[2][j]), u3 = unpack2(a1[3][j]);
            const float v0 = fmaxf(fmaxf(fmaxf(u0.x, u1.x), fmaxf(u2.x, u3.x)) + s_b1[c0 + 2*j],     0.0f);
            const float v1 = fmaxf(fmaxf(fmaxf(u0.y, u1.y), fmaxf(u2.y, u3.y)) + s_b1[c0 + 2*j + 1], 0.0f);
            hh[j] = hpack(v0, v1);
        }
    }
    __syncthreads();

    // ---- conv2 GEMM: M=112 x N=64 x K=288; 1 fp16 MMA per tile ----
    const int g  = lane >> 2;
    const int tq = lane & 3;

    float acc[8][4];
    #pragma unroll
    for (int nt = 0; nt < 8; nt++)
        #pragma unroll
        for (int q = 0; q < 4; q++) acc[nt][q] = 0.0f;

    const int r0 = wid * 16 + g;
    const int r1 = r0 + 8;
    const int crow0 = (r0 < 100) ? (r0 / 10) * 13 + (r0 % 10) : 0;
    const int crow1 = (r1 < 100) ? (r1 / 10) * 13 + (r1 % 10) : 0;

    if (wid < 7) {
        #pragma unroll 1
        for (int ks = 0; ks < 18; ks++) {
            const int tap = ks >> 1;
            const int ty = tap / 3, tx = tap - ty * 3;
            const int toff = ty * 13 + tx;
            const int j0 = ((ks & 1) << 3) + tq;

            const uint32_t* hh0 = s_hh + (crow0 + toff) * HST;
            const uint32_t* hh1 = s_hh + (crow1 + toff) * HST;
            uint32_t ah[4];
            ah[0] = hh0[j0];      ah[1] = hh1[j0];
            ah[2] = hh0[j0 + 4];  ah[3] = hh1[j0 + 4];

            #pragma unroll
            for (int nt = 0; nt < 8; nt++) {
                const uint2 f = s_wf[(ks * 8 + nt) * 32 + lane];
                uint32_t bfr[2] = { f.x, f.y };
                mma_fp16(acc[nt], ah, bfr);
            }
        }
    }

    // ---- write D to smem ----
    __syncthreads();
    if (wid < 7) {
        const int dr0 = wid * 16 + g;
        #pragma unroll
        for (int nt = 0; nt < 8; nt++) {
            const int col = nt * 8 + 2 * tq;
            *(float2*)(s_D + dr0 * 66 + col)       = make_float2(acc[nt][0], acc[nt][1]);
            *(float2*)(s_D + (dr0 + 8) * 66 + col) = make_float2(acc[nt][2], acc[nt][3]);
        }
    }
    __syncthreads();

    // ---- maxpool + bias + relu -> g_fh/g_fl ----
    if (t < 200) {
        const int cg = t / 25;
        const int pc = t - cg * 25;
        const int co0 = cg * 8;
        const int qy = pc / 5, qx = pc - qy * 5;
        const float* r0p = s_D + ((2 * qy) * 10 + 2 * qx) * 66 + co0;
        const float* r1p = r0p + 66;
        const float* r2p = s_D + ((2 * qy + 1) * 10 + 2 * qx) * 66 + co0;
        const float* r3p = r2p + 66;
        uint32_t* fh = g_fh + bb * 800 + pc * 32 + (co0 >> 1);
        uint32_t* fl = g_fl + bb * 800 + pc * 32 + (co0 >> 1);
        #pragma unroll
        for (int j = 0; j < 8; j += 2) {
            const float v0 = fmaxf(fmaxf(fmaxf(r0p[j],   r1p[j]),   fmaxf(r2p[j],   r3p[j]))   + s_b2[co0 + j],     0.0f);
            const float v1 = fmaxf(fmaxf(fmaxf(r0p[j+1], r1p[j+1]), fmaxf(r2p[j+1], r3p[j+1])) + s_b2[co0 + j + 1], 0.0f);
            const __half h0 = __float2half_rn(v0);
            const __half h1 = __float2half_rn(v1);
            const __half2 hv = __halves2half2(h0, h1);
            fh[j >> 1] = *(const uint32_t*)&hv;
            fl[j >> 1] = hpack(v0 - __half2float(h0), v1 - __half2float(h1));
        }
    }
}

// ==================== K2: head — barrier-free register-pipelined mma ====================
// 256 blocks x 32 rows; warps: s = w>>1 (k-split, 25 rounds), mt = w&1 (m-tile of 16)
__global__ __launch_bounds__(256) void moe_head_kernel(
    const float* __restrict__ gb,
    const float* __restrict__ eb,
    float* __restrict__ out)
{
    __shared__ float s_p[6 * 896];         // k-split partials (21.5KB)
    __shared__ float s_l[32 * 57];
    __shared__ float s_bias[56];

    const int t    = threadIdx.x;
    const int wid  = t >> 5;
    const int lane = t & 31;
    const int s    = wid >> 1;
    const int mt   = wid & 1;
    const int g    = lane >> 2;
    const int tq   = lane & 3;
    const int row0 = blockIdx.x * 32;

    if (t < 56) s_bias[t] = (t < 5) ? gb[t] : eb[t - 5];

    float acc[7][4];
    #pragma unroll
    for (int nt = 0; nt < 7; nt++)
        #pragma unroll
        for (int q = 0; q < 4; q++) acc[nt][q] = 0.0f;

    // direct global fragment pointers (per-thread)
    const int rowa = row0 + mt * 16 + g;
    const uint32_t* A0h = g_fh + (size_t)rowa * 800 + s * 200 + tq;
    const uint32_t* A1h = A0h + 8 * 800;
    const uint32_t* A0l = g_fl + (size_t)rowa * 800 + s * 200 + tq;
    const uint32_t* A1l = A0l + 8 * 800;
    const uint2* Bp = (const uint2*)g_hfrag + (size_t)(s * 25) * 224 + lane;

    uint32_t ah[2][4], al[2][4];
    uint2 bf[2][7];

    // prefetch round 0
    {
        ah[0][0] = A0h[0];  ah[0][1] = A1h[0];  ah[0][2] = A0h[4];  ah[0][3] = A1h[4];
        al[0][0] = A0l[0];  al[0][1] = A1l[0];  al[0][2] = A0l[4];  al[0][3] = A1l[4];
        #pragma unroll
        for (int nt = 0; nt < 7; nt++) bf[0][nt] = Bp[nt * 32];
    }

    #pragma unroll 1
    for (int r = 0; r < 25; r++) {
        const int cur = r & 1, nxt = cur ^ 1;
        if (r < 24) {
            const int ro = (r + 1) * 8;
            ah[nxt][0] = A0h[ro];      ah[nxt][1] = A1h[ro];
            ah[nxt][2] = A0h[ro + 4];  ah[nxt][3] = A1h[ro + 4];
            al[nxt][0] = A0l[ro];      al[nxt][1] = A1l[ro];
            al[nxt][2] = A0l[ro + 4];  al[nxt][3] = A1l[ro + 4];
            #pragma unroll
            for (int nt = 0; nt < 7; nt++) bf[nxt][nt] = Bp[(r + 1) * 224 + nt * 32];
        }
        #pragma unroll
        for (int nt = 0; nt < 7; nt++) {
            uint32_t bfr[2] = { bf[cur][nt].x, bf[cur][nt].y };
            mma_fp16(acc[nt], ah[cur], bfr);
            mma_fp16(acc[nt], al[cur], bfr);
        }
    }

    // ---- k-split reduction via smem ----
    if (s > 0) {
        float* pp = s_p + ((s - 1) * 2 + mt) * 896;
        #pragma unroll
        for (int nt = 0; nt < 7; nt++)
            #pragma unroll
            for (int q = 0; q < 4; q++)
                pp[(nt * 4 + q) * 32 + lane] = acc[nt][q];
    }
    __syncthreads();
    if (s == 0) {
        #pragma unroll
        for (int q3 = 0; q3 < 3; q3++) {
            const float* pp = s_p + (q3 * 2 + mt) * 896;
            #pragma unroll
            for (int nt = 0; nt < 7; nt++)
                #pragma unroll
                for (int q = 0; q < 4; q++)
                    acc[nt][q] += pp[(nt * 4 + q) * 32 + lane];
        }
        const int row = mt * 16 + g;
        #pragma unroll
        for (int nt = 0; nt < 7; nt++) {
            const int col = nt * 8 + 2 * tq;
            s_l[row * 57 + col]           = acc[nt][0] + s_bias[col];
            s_l[row * 57 + col + 1]       = acc[nt][1] + s_bias[col + 1];
            s_l[(row + 8) * 57 + col]     = acc[nt][2] + s_bias[col];
            s_l[(row + 8) * 57 + col + 1] = acc[nt][3] + s_bias[col + 1];
        }
    }
    __syncthreads();

    // ---- per-row MoE epilogue ----
    if (t < 32) {
        const float* L = s_l + t * 57;
        float p[5];
        float gm = -1e30f;
        #pragma unroll
        for (int e = 0; e < 5; e++) gm = fmaxf(gm, L[e]);
        float gsum = 0.0f;
        #pragma unroll
        for (int e = 0; e < 5; e++) { p[e] = expf(L[e] - gm); gsum += p[e]; }
        const float ginv = 1.0f / gsum;
        #pragma unroll
        for (int e = 0; e < 5; e++) p[e] *= ginv;

        int idx[5] = {0, 1, 2, 3, 4};
        #pragma unroll
        for (int a = 0; a < 3; a++) {
            int best = a;
            #pragma unroll
            for (int q = a + 1; q < 5; q++)
                if (p[idx[q]] > p[idx[best]]) best = q;
            const int tmp = idx[a]; idx[a] = idx[best]; idx[best] = tmp;
        }

        float comb[10];
        #pragma unroll
        for (int c = 0; c < 10; c++) {
            float v = 0.0f;
            #pragma unroll
            for (int k = 0; k < 3; k++)
                v = fmaf(p[idx[k]], L[5 + idx[k] * 10 + c], v);
            comb[c] = v;
        }
        float cm = -1e30f;
        #pragma unroll
        for (int c = 0; c < 10; c++) cm = fmaxf(cm, comb[c]);
        float cs = 0.0f;
        float ex[10];
        #pragma unroll
        for (int c = 0; c < 10; c++) { ex[c] = expf(comb[c] - cm); cs += ex[c]; }
        const float inv = 1.0f / cs;
        float* o = out + (row0 + t) * 10;
        #pragma unroll
        for (int c = 0; c < 10; c++) o[c] = ex[c] * inv;
    }
}

// ==================== launcher ====================
extern "C" void kernel_launch(void* const* d_in, const int* in_sizes, int n_in,
                              void* d_out, int out_size) {
    const float* x  = (const float*)d_in[0];
    const float* w1 = (const float*)d_in[1];
    const float* b1 = (const float*)d_in[2];
    const float* w2 = (const float*)d_in[3];
    const float* b2 = (const float*)d_in[4];
    const float* gw = (const float*)d_in[5];
    const float* gb = (const float*)d_in[6];
    const float* ew = (const float*)d_in[7];
    const float* eb = (const float*)d_in[8];
    float* out = (float*)d_out;

    cudaFuncSetAttribute(conv_mma_kernel,
                         cudaFuncAttributeMaxDynamicSharedMemorySize, SM_TOTAL);

    prep_wfrag_kernel<<<(18 * 8 * 32 + 255) / 256, 256>>>(w2);
    prep_hfrag_kernel<<<(100 * 7 * 32 + 255) / 256, 256>>>(gw, ew);
    conv_mma_kernel<<<B, 256, SM_TOTAL>>>(x, w1, b1, b2);
    moe_head_kernel<<<B / 32, 256>>>(gb, eb, out);
}